// round 9
// baseline (speedup 1.0000x reference)
#include <cuda_runtime.h>
#include <cuda_bf16.h>
#include <stdint.h>
#include <string.h>
#include <math.h>

#define EMB   300
#define EMB2  600
#define NG    4096
#define NL    5
#define MAXN  100000
#define MAXE  400000
#define BN_EPS 1e-5f
#define INV_TEMP 25.0f

#define KP1  320    // padded K for K=300 (10 chunks of 32)
#define NKC1 10
#define KP2  608    // padded K for K=600 (19 chunks of 32)
#define NKC2 19

// B block tables: per block [128 n-rows x 40 bf16] (32 data + 8 pad) = 5120 bf16
// = exact smem tile layout (row stride 20 u32), so staging is a flat copy.
#define BLKSZ 5120
#define OFF_W1(l) ((size_t)(l) * 50 * BLKSZ)
#define OFF_W2(l) ((size_t)1280000 + (size_t)(l) * 57 * BLKSZ)
#define OFF_PJ    ((size_t)2739200)
#define OFF_F1    ((size_t)2892800)
#define BT_TOTAL  4531200

typedef __nv_bfloat16 bf16;

// ---------------- scratch (device globals; no allocation allowed) -----------
__device__ float g_h    [(size_t)MAXN * EMB];
__device__ float g_agg  [(size_t)MAXN * EMB];
__device__ float g_stats[2 * EMB];
__device__ float g_feat0[(size_t)NG * EMB];
__device__ float g_feat1[(size_t)NG * EMB];
__device__ float g_cnt  [NG];
__device__ float g_etab [(size_t)NL * 18 * EMB];
__device__ bf16  g_ahi  [(size_t)MAXN * KP1];   // agg / h3 (hi)
__device__ bf16  g_alo  [(size_t)MAXN * KP1];   // agg / h3 (lo)
__device__ bf16  g_h2hi [(size_t)MAXN * KP2];
__device__ bf16  g_h2lo [(size_t)MAXN * KP2];
__device__ bf16  g_f0hi [(size_t)NG * KP1];
__device__ bf16  g_f0lo [(size_t)NG * KP1];
__device__ bf16  g_bthi [BT_TOTAL];
__device__ bf16  g_btlo [BT_TOTAL];
__device__ int   g_off  [MAXN + 1];
__device__ int   g_cur  [MAXN];
__device__ int   g_bsum [256];
__device__ int   g_csr  [MAXE];

// ---------------- helpers -----------------------------------------------------
__device__ __forceinline__ uint32_t smem_addr_u32(const void* p) {
    uint32_t a;
    asm("{ .reg .u64 t; cvta.to.shared.u64 t, %1; cvt.u32.u64 %0, t; }" : "=r"(a) : "l"(p));
    return a;
}
__device__ __forceinline__ void cp16(uint32_t d, const void* s, int pred) {
    asm volatile("{\n\t.reg .pred p;\n\tsetp.ne.b32 p, %2, 0;\n\t"
                 "@p cp.async.cg.shared.global [%0], [%1], 16;\n\t}"
                 :: "r"(d), "l"(s), "r"(pred));
}
__device__ __forceinline__ uint32_t lds32(uint32_t a) {
    uint32_t v;
    asm volatile("ld.shared.b32 %0, [%1];" : "=r"(v) : "r"(a));
    return v;
}
__device__ __forceinline__ void mma_bf16(float* c, const uint32_t* a, const uint32_t* b) {
    asm volatile(
        "mma.sync.aligned.m16n8k16.row.col.f32.bf16.bf16.f32 "
        "{%0,%1,%2,%3},{%4,%5,%6,%7},{%8,%9},{%0,%1,%2,%3};"
        : "+f"(c[0]), "+f"(c[1]), "+f"(c[2]), "+f"(c[3])
        : "r"(a[0]), "r"(a[1]), "r"(a[2]), "r"(a[3]), "r"(b[0]), "r"(b[1]));
}
__device__ __forceinline__ uint32_t packbf(float a, float b) {
    __nv_bfloat162 t = __floats2bfloat162_rn(a, b);
    uint32_t r; memcpy(&r, &t, 4); return r;
}

// ---------------- small utility kernels -------------------------------------
__global__ void zero_f(float* p, int n) {
    int i = blockIdx.x * blockDim.x + threadIdx.x;
    if (i < n) p[i] = 0.f;
}
__global__ void zero_i(int* p, int n) {
    int i = blockIdx.x * blockDim.x + threadIdx.x;
    if (i < n) p[i] = 0;
}

__global__ void init_h_kernel(const int* __restrict__ x,
                              const float* __restrict__ ae1,
                              const float* __restrict__ ae2,
                              float* __restrict__ h, int n) {
    int idx = blockIdx.x * blockDim.x + threadIdx.x;
    if (idx >= n * EMB) return;
    int i = idx / EMB, c = idx - i * EMB;
    h[idx] = ae1[x[2 * i] * EMB + c] + ae2[x[2 * i + 1] * EMB + c];
}

__global__ void etab_kernel(const float* __restrict__ ee1,
                            const float* __restrict__ ee2,
                            float* __restrict__ et) {
    int idx = blockIdx.x * blockDim.x + threadIdx.x;
    if (idx >= NL * 18 * EMB) return;
    int l = idx / (18 * EMB);
    int r = idx - l * 18 * EMB;
    int combo = r / EMB, c = r - combo * EMB;
    int a0 = combo / 3, a1 = combo - a0 * 3;
    et[idx] = ee1[(size_t)l * 6 * EMB + a0 * EMB + c] +
              ee2[(size_t)l * 3 * EMB + a1 * EMB + c];
}

// ---------------- B table conversion ------------------------------------------
// src: trans=0 -> [K,N] row-major (weights), trans=1 -> [N,K] row-major (f1).
// block = ntile*nkc + kc; within: r = n%128, c = k%32; e = block*5120 + r*40 + c.
__global__ void conv_btab_kernel(const float* __restrict__ src,
                                 bf16* __restrict__ thi, bf16* __restrict__ tlo,
                                 int N, int K, int nkc, int trans, int total) {
    int idx = blockIdx.x * blockDim.x + threadIdx.x;
    if (idx >= total) return;
    int block  = idx >> 12;           // 4096 data elems per block
    int within = idx & 4095;
    int r = within >> 5, c = within & 31;
    int ntile = block / nkc, kc = block - ntile * nkc;
    int n = ntile * 128 + r;
    int k = kc * 32 + c;
    float v = 0.f;
    if (n < N && k < K)
        v = trans ? src[(size_t)n * K + k] : src[(size_t)k * N + n];
    bf16 h = __float2bfloat16_rn(v);
    size_t e = (size_t)block * BLKSZ + r * 40 + c;
    thi[e] = h;
    tlo[e] = __float2bfloat16_rn(v - __bfloat162float(h));
}

// feat0 fp32 -> hi/lo bf16 [NG, KP1]
__global__ void conv_f0_kernel(const float* __restrict__ f,
                               bf16* __restrict__ fh, bf16* __restrict__ fl) {
    int idx = blockIdx.x * blockDim.x + threadIdx.x;
    if (idx >= NG * EMB) return;
    int m = idx / EMB, k = idx - m * EMB;
    float v = f[idx];
    bf16 h = __float2bfloat16_rn(v);
    fh[(size_t)m * KP1 + k] = h;
    fl[(size_t)m * KP1 + k] = __float2bfloat16_rn(v - __bfloat162float(h));
}

// ---------------- hi/lo bf16 GEMM (mma.sync + cp.async pipeline) --------------
// C = act(alpha * (Ah+Al) @ (Bh+Bl) + bias), 3-term compensated.
// Block tile 128x128, BK=32, 8 warps (4m x 2n), warp tile 32x64. 4 smem stages,
// single __syncthreads per chunk.
#define STAGE_B   40960   // A_hi 10240 | A_lo 10240 | B_hi 10240 | B_lo 10240
#define GEMM_SMEM (4 * STAGE_B)

__global__ __launch_bounds__(256)
void gemm_hl_kernel(const bf16* __restrict__ Ahi, const bf16* __restrict__ Alo,
                    int Kpad, int nk,
                    const bf16* __restrict__ Bh, const bf16* __restrict__ Bl,
                    const float* __restrict__ bias,
                    float* __restrict__ Cf,
                    bf16* __restrict__ C3hi, bf16* __restrict__ C3lo, int K3out,
                    int M, int N, float alpha, int do_relu) {
    extern __shared__ uint32_t smem[];
    uint32_t sb = smem_addr_u32(smem);

    int tid = threadIdx.x, wid = tid >> 5, lane = tid & 31;
    int g = lane >> 2, tig = lane & 3;
    int wm = (wid & 3) * 32, wn = (wid >> 2) * 64;
    int bm0 = blockIdx.y * 128, bn0 = blockIdx.x * 128;

    float acc[2][8][4];
#pragma unroll
    for (int mt = 0; mt < 2; mt++)
#pragma unroll
        for (int nt = 0; nt < 8; nt++)
#pragma unroll
            for (int q = 0; q < 4; q++) acc[mt][nt][q] = 0.f;

    auto load_stage = [&](int kc, int s) {
        uint32_t base = sb + s * STAGE_B;
        // A: 128 rows x 32 k (hi+lo), row stride 80B, 4 chunks/row
#pragma unroll
        for (int it = 0; it < 2; it++) {
            int idx = tid + it * 256;             // 0..511
            int row = idx >> 2, ch = idx & 3;
            int gm = bm0 + row;
            int pred = gm < M;
            size_t so = (size_t)gm * Kpad + kc * 32 + ch * 8;
            uint32_t d = base + row * 80 + ch * 16;
            cp16(d, Ahi + so, pred);
            cp16(d + 10240, Alo + so, pred);
        }
        // B: flat 10240B block copies (tables pre-laid-out, 128 rows x 80B)
        const bf16* bh = Bh + (size_t)(blockIdx.x * nk + kc) * BLKSZ;
        const bf16* bl = Bl + (size_t)(blockIdx.x * nk + kc) * BLKSZ;
#pragma unroll
        for (int it = 0; it < 3; it++) {
            int idx = tid + it * 256;             // 0..767, need < 640
            int pred = idx < 640;
            cp16(base + 20480 + idx * 16, bh + idx * 8, pred);
            cp16(base + 30720 + idx * 16, bl + idx * 8, pred);
        }
        asm volatile("cp.async.commit_group;" ::: "memory");
    };

    load_stage(0, 0);
    load_stage(1, 1);
    load_stage(2, 2);

    for (int kc = 0; kc < nk; kc++) {
        asm volatile("cp.async.wait_group 2;" ::: "memory");
        __syncthreads();
        if (kc + 3 < nk) load_stage(kc + 3, (kc + 3) & 3);
        uint32_t base = sb + (kc & 3) * STAGE_B;
        uint32_t aHi = base, aLo = base + 10240;
        uint32_t bHi = base + 20480, bLo = base + 30720;
#pragma unroll
        for (int s = 0; s < 2; s++) {
            int kk4 = (s * 8 + tig) * 4;          // byte offset of k-pair
            uint32_t ah[2][4], al[2][4], bh[8][2], bl[8][2];
#pragma unroll
            for (int mt = 0; mt < 2; mt++) {
                uint32_t r0 = (wm + mt * 16 + g) * 80;
                uint32_t r1 = r0 + 8 * 80;
                ah[mt][0] = lds32(aHi + r0 + kk4);
                ah[mt][1] = lds32(aHi + r1 + kk4);
                ah[mt][2] = lds32(aHi + r0 + kk4 + 16);
                ah[mt][3] = lds32(aHi + r1 + kk4 + 16);
                al[mt][0] = lds32(aLo + r0 + kk4);
                al[mt][1] = lds32(aLo + r1 + kk4);
                al[mt][2] = lds32(aLo + r0 + kk4 + 16);
                al[mt][3] = lds32(aLo + r1 + kk4 + 16);
            }
#pragma unroll
            for (int nt = 0; nt < 8; nt++) {
                uint32_t c0 = (wn + nt * 8 + g) * 80;
                bh[nt][0] = lds32(bHi + c0 + kk4);
                bh[nt][1] = lds32(bHi + c0 + kk4 + 16);
                bl[nt][0] = lds32(bLo + c0 + kk4);
                bl[nt][1] = lds32(bLo + c0 + kk4 + 16);
            }
#pragma unroll
            for (int mt = 0; mt < 2; mt++)
#pragma unroll
                for (int nt = 0; nt < 8; nt++) {
                    mma_bf16(acc[mt][nt], ah[mt], bl[nt]);
                    mma_bf16(acc[mt][nt], al[mt], bh[nt]);
                    mma_bf16(acc[mt][nt], ah[mt], bh[nt]);
                }
        }
    }
    asm volatile("cp.async.wait_group 0;" ::: "memory");

    // ---- epilogue ----
#pragma unroll
    for (int mt = 0; mt < 2; mt++) {
        int gmB = bm0 + wm + mt * 16 + g;
#pragma unroll
        for (int nt = 0; nt < 8; nt++) {
            int n0 = bn0 + wn + nt * 8 + tig * 2;
            float* a = acc[mt][nt];
#pragma unroll
            for (int hf = 0; hf < 2; hf++) {
                int gm = gmB + hf * 8;
                if (gm >= M || n0 >= N) continue;
                float v0 = a[hf * 2] * alpha, v1 = a[hf * 2 + 1] * alpha;
                if (bias) { v0 += bias[n0]; v1 += bias[n0 + 1]; }
                if (do_relu) { v0 = fmaxf(v0, 0.f); v1 = fmaxf(v1, 0.f); }
                if (Cf) {
                    Cf[(size_t)gm * N + n0]     = v0;
                    Cf[(size_t)gm * N + n0 + 1] = v1;
                }
                if (C3hi) {
                    float h0 = __bfloat162float(__float2bfloat16_rn(v0));
                    float h1 = __bfloat162float(__float2bfloat16_rn(v1));
                    *(uint32_t*)(C3hi + (size_t)gm * K3out + n0) = packbf(h0, h1);
                    *(uint32_t*)(C3lo + (size_t)gm * K3out + n0) =
                        packbf(v0 - h0, v1 - h1);
                }
            }
        }
    }
}

// ---------------- CSR build ---------------------------------------------------
__global__ void count_deg_kernel(const int* __restrict__ ei, int* __restrict__ deg,
                                 int E) {
    int e = blockIdx.x * blockDim.x + threadIdx.x;
    if (e < E) atomicAdd(&deg[ei[E + e]], 1);
}

__global__ void scan1_kernel(const int* __restrict__ deg, int* __restrict__ off,
                             int* __restrict__ bsum, int n) {
    __shared__ int s[1024];
    int t = threadIdx.x;
    int i = blockIdx.x * 1024 + t;
    int v = (i < n) ? deg[i] : 0;
    s[t] = v;
    __syncthreads();
    for (int o = 1; o < 1024; o <<= 1) {
        int add = (t >= o) ? s[t - o] : 0;
        __syncthreads();
        s[t] += add;
        __syncthreads();
    }
    if (i < n) off[i + 1] = s[t];
    if (t == 1023) bsum[blockIdx.x] = s[1023];
}

__global__ void scan2_kernel(int* bsum, int G) {
    if (threadIdx.x == 0 && blockIdx.x == 0) {
        int run = 0;
        for (int b = 0; b < G; b++) { int v = bsum[b]; bsum[b] = run; run += v; }
    }
}

__global__ void scan3_kernel(int* __restrict__ off, const int* __restrict__ bsum,
                             int n) {
    int i = blockIdx.x * 1024 + threadIdx.x;
    if (i < n) off[i + 1] += bsum[blockIdx.x];
    if (i == 0) off[0] = 0;
}

__global__ void copy_cur_kernel(const int* __restrict__ off, int* __restrict__ cur,
                                int n) {
    int i = blockIdx.x * blockDim.x + threadIdx.x;
    if (i < n) cur[i] = off[i];
}

__global__ void fill_csr_kernel(const int* __restrict__ ei, const int* __restrict__ ea,
                                int* __restrict__ cur, int* __restrict__ csr, int E) {
    int e = blockIdx.x * blockDim.x + threadIdx.x;
    if (e >= E) return;
    int d = ei[E + e];
    int p = atomicAdd(&cur[d], 1);
    int a = ea[2 * e] * 3 + ea[2 * e + 1];
    csr[p] = ei[e] | (a << 20);
}

// ---------------- message aggregation: gather -> hi/lo bf16 -------------------
__global__ void gather_kernel(const float* __restrict__ h,
                              const int* __restrict__ off,
                              const int* __restrict__ csr,
                              const float* __restrict__ et,
                              bf16* __restrict__ ahi, bf16* __restrict__ alo,
                              int n) {
    int w    = (blockIdx.x * blockDim.x + threadIdx.x) >> 5;
    int lane = threadIdx.x & 31;
    if (w >= n) return;
    int o0 = off[w], o1 = off[w + 1];
    const float* hd    = h + (size_t)w * EMB;
    const float* selft = et + 12 * EMB;
    float r[10];
#pragma unroll
    for (int j = 0; j < 10; j++) {
        int c = lane + 32 * j;
        r[j] = (c < EMB) ? hd[c] + selft[c] : 0.f;
    }
    for (int o = o0; o < o1; o++) {
        int pk = csr[o];
        const float* hs = h  + (size_t)(pk & 0xFFFFF) * EMB;
        const float* tt = et + (size_t)(pk >> 20) * EMB;
#pragma unroll
        for (int j = 0; j < 10; j++) {
            int c = lane + 32 * j;
            if (c < EMB) r[j] += hs[c] + tt[c];
        }
    }
    bf16* rh = ahi + (size_t)w * KP1;
    bf16* rl = alo + (size_t)w * KP1;
#pragma unroll
    for (int j = 0; j < 10; j++) {
        int c = lane + 32 * j;
        if (c < EMB) {
            bf16 hh = __float2bfloat16_rn(r[j]);
            rh[c] = hh;
            rl[c] = __float2bfloat16_rn(r[j] - __bfloat162float(hh));
        }
    }
}

// ---------------- batchnorm ---------------------------------------------------
__global__ void bn_stats_kernel(const float* __restrict__ h, float* __restrict__ stats,
                                int n) {
    int t = threadIdx.x;
    if (t >= EMB) return;
    float s = 0.f, sq = 0.f;
    for (int r = blockIdx.x; r < n; r += gridDim.x) {
        float v = h[(size_t)r * EMB + t];
        s += v; sq += v * v;
    }
    atomicAdd(&stats[t], s);
    atomicAdd(&stats[EMB + t], sq);
}

// last layer additionally emits hi/lo bf16 for projector input
__global__ void bn_apply_kernel(float* __restrict__ h, const float* __restrict__ stats,
                                const float* __restrict__ gamma,
                                const float* __restrict__ beta,
                                int n, int do_relu,
                                bf16* __restrict__ ahi, bf16* __restrict__ alo) {
    int idx = blockIdx.x * blockDim.x + threadIdx.x;
    if (idx >= n * EMB) return;
    int i = idx / EMB, c = idx - i * EMB;
    float invn = 1.f / (float)n;
    float mean = stats[c] * invn;
    float var  = stats[EMB + c] * invn - mean * mean;
    float inv  = rsqrtf(var + BN_EPS);
    float v = (h[idx] - mean) * inv * gamma[c] + beta[c];
    if (do_relu) v = fmaxf(v, 0.f);
    h[idx] = v;
    if (ahi) {
        bf16 hh = __float2bfloat16_rn(v);
        ahi[(size_t)i * KP1 + c] = hh;
        alo[(size_t)i * KP1 + c] = __float2bfloat16_rn(v - __bfloat162float(hh));
    }
}

// ---------------- pooling + normalize ----------------------------------------
__global__ void pool_kernel(const float* __restrict__ p, const int* __restrict__ batch,
                            float* __restrict__ feat, float* __restrict__ cnt, int n) {
    int gw   = (blockIdx.x * blockDim.x + threadIdx.x) >> 5;
    int lane = threadIdx.x & 31;
    if (gw >= n) return;
    int b = batch[gw];
    if (lane == 0) atomicAdd(&cnt[b], 1.f);
    const float* pr = p + (size_t)gw * EMB;
    float* fr = feat + (size_t)b * EMB;
    for (int c = lane; c < EMB; c += 32) atomicAdd(fr + c, pr[c]);
}

__global__ void norm_feat_kernel(float* __restrict__ feat, const float* __restrict__ cnt) {
    __shared__ float red[16];
    int g = blockIdx.x, t = threadIdx.x;
    float c = fmaxf(cnt[g], 1.f);
    float v = 0.f;
    if (t < EMB) v = feat[(size_t)g * EMB + t] / c;
    float sq = v * v;
#pragma unroll
    for (int o = 16; o; o >>= 1) sq += __shfl_xor_sync(0xffffffffu, sq, o);
    if ((t & 31) == 0) red[t >> 5] = sq;
    __syncthreads();
    if (t < 32) {
        float s = (t < (int)(blockDim.x >> 5)) ? red[t] : 0.f;
#pragma unroll
        for (int o = 16; o; o >>= 1) s += __shfl_xor_sync(0xffffffffu, s, o);
        if (t == 0) red[0] = s;
    }
    __syncthreads();
    float nrm = fmaxf(sqrtf(red[0]), 1e-12f);
    if (t < EMB) feat[(size_t)g * EMB + t] = v / nrm;
}

// ---------------- driver ------------------------------------------------------
extern "C" void kernel_launch(void* const* d_in, const int* in_sizes, int n_in,
                              void* d_out, int out_size) {
    const int* x[2]  = {(const int*)d_in[0], (const int*)d_in[4]};
    const int* ei[2] = {(const int*)d_in[1], (const int*)d_in[5]};
    const int* ea[2] = {(const int*)d_in[2], (const int*)d_in[6]};
    const int* bt[2] = {(const int*)d_in[3], (const int*)d_in[7]};
    const float* ae1 = (const float*)d_in[8];
    const float* ae2 = (const float*)d_in[9];
    const float* ee1 = (const float*)d_in[10];
    const float* ee2 = (const float*)d_in[11];
    const float* w1  = (const float*)d_in[12];
    const float* b1  = (const float*)d_in[13];
    const float* w2  = (const float*)d_in[14];
    const float* b2  = (const float*)d_in[15];
    const float* gam = (const float*)d_in[16];
    const float* bet = (const float*)d_in[17];
    const float* pw  = (const float*)d_in[18];
    const float* pb  = (const float*)d_in[19];

    int Nn[2] = {in_sizes[0] / 2, in_sizes[4] / 2};
    int Ee[2] = {in_sizes[1] / 2, in_sizes[5] / 2};

    float *h, *agg, *stats, *feat0, *feat1, *cnt, *et;
    bf16 *ahi, *alo, *h2hi, *h2lo, *f0hi, *f0lo, *bthi, *btlo;
    int *off, *cur, *bsum, *csr;
    cudaGetSymbolAddress((void**)&h,     g_h);
    cudaGetSymbolAddress((void**)&agg,   g_agg);
    cudaGetSymbolAddress((void**)&stats, g_stats);
    cudaGetSymbolAddress((void**)&feat0, g_feat0);
    cudaGetSymbolAddress((void**)&feat1, g_feat1);
    cudaGetSymbolAddress((void**)&cnt,   g_cnt);
    cudaGetSymbolAddress((void**)&et,    g_etab);
    cudaGetSymbolAddress((void**)&ahi,   g_ahi);
    cudaGetSymbolAddress((void**)&alo,   g_alo);
    cudaGetSymbolAddress((void**)&h2hi,  g_h2hi);
    cudaGetSymbolAddress((void**)&h2lo,  g_h2lo);
    cudaGetSymbolAddress((void**)&f0hi,  g_f0hi);
    cudaGetSymbolAddress((void**)&f0lo,  g_f0lo);
    cudaGetSymbolAddress((void**)&bthi,  g_bthi);
    cudaGetSymbolAddress((void**)&btlo,  g_btlo);
    cudaGetSymbolAddress((void**)&off,   g_off);
    cudaGetSymbolAddress((void**)&cur,   g_cur);
    cudaGetSymbolAddress((void**)&bsum,  g_bsum);
    cudaGetSymbolAddress((void**)&csr,   g_csr);

    cudaFuncSetAttribute(gemm_hl_kernel,
                         cudaFuncAttributeMaxDynamicSharedMemorySize, GEMM_SMEM);

    etab_kernel<<<(NL * 18 * EMB + 255) / 256, 256>>>(ee1, ee2, et);

    // weight tables: hi/lo, smem-layout blocks ([128n x 32k] per block)
    for (int l = 0; l < NL; l++) {
        conv_btab_kernel<<<(50 * 4096 + 255) / 256, 256>>>(
            w1 + (size_t)l * EMB * EMB2, bthi + OFF_W1(l), btlo + OFF_W1(l),
            EMB2, EMB, NKC1, 0, 50 * 4096);
        conv_btab_kernel<<<(57 * 4096 + 255) / 256, 256>>>(
            w2 + (size_t)l * EMB2 * EMB, bthi + OFF_W2(l), btlo + OFF_W2(l),
            EMB, EMB2, NKC2, 0, 57 * 4096);
    }
    conv_btab_kernel<<<(30 * 4096 + 255) / 256, 256>>>(
        pw, bthi + OFF_PJ, btlo + OFF_PJ, EMB, EMB, NKC1, 0, 30 * 4096);

    for (int br = 0; br < 2; br++) {
        int n = Nn[br], e = Ee[br];
        float* feat_b = br ? feat1 : feat0;
        int elemBlocks = (n * EMB + 255) / 256;
        int G = (n + 1023) / 1024;
        int mt = (n + 127) / 128;

        // CSR (dst adjacency)
        zero_i<<<(n + 255) / 256, 256>>>(cur, n);
        count_deg_kernel<<<(e + 255) / 256, 256>>>(ei[br], cur, e);
        scan1_kernel<<<G, 1024>>>(cur, off, bsum, n);
        scan2_kernel<<<1, 32>>>(bsum, G);
        scan3_kernel<<<G, 1024>>>(off, bsum, n);
        copy_cur_kernel<<<(n + 255) / 256, 256>>>(off, cur, n);
        fill_csr_kernel<<<(e + 255) / 256, 256>>>(ei[br], ea[br], cur, csr, e);

        init_h_kernel<<<elemBlocks, 256>>>(x[br], ae1, ae2, h, n);

        for (int l = 0; l < NL; l++) {
            const float* etl = et + (size_t)l * 18 * EMB;

            gather_kernel<<<(n + 7) / 8, 256>>>(h, off, csr, etl, ahi, alo, n);

            // h2 = relu(agg @ W1 + b1) -> hi/lo bf16
            gemm_hl_kernel<<<dim3(5, mt), 256, GEMM_SMEM>>>(
                ahi, alo, KP1, NKC1, bthi + OFF_W1(l), btlo + OFF_W1(l),
                b1 + (size_t)l * EMB2, nullptr, h2hi, h2lo, KP2,
                n, EMB2, 1.f, 1);
            // h = h2 @ W2 + b2 (fp32)
            gemm_hl_kernel<<<dim3(3, mt), 256, GEMM_SMEM>>>(
                h2hi, h2lo, KP2, NKC2, bthi + OFF_W2(l), btlo + OFF_W2(l),
                b2 + (size_t)l * EMB, h, nullptr, nullptr, 0,
                n, EMB, 1.f, 0);

            zero_f<<<(2 * EMB + 255) / 256, 256>>>(stats, 2 * EMB);
            bn_stats_kernel<<<512, 320>>>(h, stats, n);
            bn_apply_kernel<<<elemBlocks, 256>>>(
                h, stats, gam + (size_t)l * EMB, bet + (size_t)l * EMB,
                n, l != NL - 1,
                (l == NL - 1) ? ahi : nullptr, (l == NL - 1) ? alo : nullptr);
        }

        // projector: agg = h @ proj_w + proj_b
        gemm_hl_kernel<<<dim3(3, mt), 256, GEMM_SMEM>>>(
            ahi, alo, KP1, NKC1, bthi + OFF_PJ, btlo + OFF_PJ,
            pb, agg, nullptr, nullptr, 0, n, EMB, 1.f, 0);

        zero_f<<<(NG * EMB + 255) / 256, 256>>>(feat_b, NG * EMB);
        zero_f<<<(NG + 255) / 256, 256>>>(cnt, NG);
        pool_kernel<<<(n * 32 + 255) / 256, 256>>>(agg, bt[br], feat_b, cnt, n);
        norm_feat_kernel<<<NG, 320>>>(feat_b, cnt);
    }

    // logits = f0 @ f1^T / TEMP
    conv_btab_kernel<<<(320 * 4096 + 255) / 256, 256>>>(
        feat1, bthi + OFF_F1, btlo + OFF_F1, NG, EMB, NKC1, 1, 320 * 4096);
    conv_f0_kernel<<<(NG * EMB + 255) / 256, 256>>>(feat0, f0hi, f0lo);
    gemm_hl_kernel<<<dim3(32, 32), 256, GEMM_SMEM>>>(
        f0hi, f0lo, KP1, NKC1, bthi + OFF_F1, btlo + OFF_F1,
        nullptr, (float*)d_out, nullptr, nullptr, 0,
        NG, NG, INV_TEMP, 0);
}

// round 10
// speedup vs baseline: 1.1647x; 1.1647x over previous
#include <cuda_runtime.h>
#include <cuda_bf16.h>
#include <stdint.h>
#include <string.h>
#include <math.h>

#define EMB   300
#define EMB2  600
#define NG    4096
#define NL    5
#define MAXN  100000
#define MAXE  400000
#define BN_EPS 1e-5f
#define INV_TEMP 25.0f

#define KP1  320    // padded K for K=300 (10 chunks of 32)
#define NKC1 10
#define KP2  608    // padded K for K=600 (19 chunks of 32)
#define NKC2 19

// B block tables: per block [64 n-rows x 40 bf16] (32 data + 8 pad) = 2560 bf16
// = exact smem tile layout (row stride 20 u32), so staging is a flat copy.
#define BLKSZ 2560
#define OFF_W1(l) ((size_t)(l) * 100 * BLKSZ)
#define OFF_W2(l) ((size_t)1280000 + (size_t)(l) * 95 * BLKSZ)
#define OFF_PJ    ((size_t)2496000)
#define OFF_F1    ((size_t)2624000)
#define BT_TOTAL  4262400

typedef __nv_bfloat16 bf16;

// ---------------- scratch (device globals; no allocation allowed) -----------
__device__ float g_h    [(size_t)MAXN * EMB];
__device__ float g_agg  [(size_t)MAXN * EMB];
__device__ float g_stats[2 * EMB];
__device__ float g_feat0[(size_t)NG * EMB];
__device__ float g_feat1[(size_t)NG * EMB];
__device__ float g_cnt  [NG];
__device__ float g_etab [(size_t)NL * 18 * EMB];
__device__ bf16  g_ahi  [(size_t)MAXN * KP1];   // agg / h3 (hi)
__device__ bf16  g_alo  [(size_t)MAXN * KP1];   // agg / h3 (lo)
__device__ bf16  g_h2hi [(size_t)MAXN * KP2];
__device__ bf16  g_h2lo [(size_t)MAXN * KP2];
__device__ bf16  g_f0hi [(size_t)NG * KP1];
__device__ bf16  g_f0lo [(size_t)NG * KP1];
__device__ bf16  g_bthi [BT_TOTAL];
__device__ bf16  g_btlo [BT_TOTAL];
__device__ int   g_off  [MAXN + 1];
__device__ int   g_cur  [MAXN];
__device__ int   g_bsum [256];
__device__ int   g_csr  [MAXE];

// ---------------- helpers -----------------------------------------------------
__device__ __forceinline__ uint32_t smem_addr_u32(const void* p) {
    uint32_t a;
    asm("{ .reg .u64 t; cvta.to.shared.u64 t, %1; cvt.u32.u64 %0, t; }" : "=r"(a) : "l"(p));
    return a;
}
__device__ __forceinline__ void cp16(uint32_t d, const void* s, int pred) {
    asm volatile("{\n\t.reg .pred p;\n\tsetp.ne.b32 p, %2, 0;\n\t"
                 "@p cp.async.cg.shared.global [%0], [%1], 16;\n\t}"
                 :: "r"(d), "l"(s), "r"(pred));
}
#define LDSM4(r0, r1, r2, r3, addr) \
    asm volatile("ldmatrix.sync.aligned.m8n8.x4.shared.b16 {%0,%1,%2,%3}, [%4];" \
                 : "=r"(r0), "=r"(r1), "=r"(r2), "=r"(r3) : "r"(addr))
__device__ __forceinline__ void mma_bf16(float* c, const uint32_t* a, const uint32_t* b) {
    asm volatile(
        "mma.sync.aligned.m16n8k16.row.col.f32.bf16.bf16.f32 "
        "{%0,%1,%2,%3},{%4,%5,%6,%7},{%8,%9},{%0,%1,%2,%3};"
        : "+f"(c[0]), "+f"(c[1]), "+f"(c[2]), "+f"(c[3])
        : "r"(a[0]), "r"(a[1]), "r"(a[2]), "r"(a[3]), "r"(b[0]), "r"(b[1]));
}
__device__ __forceinline__ uint32_t packbf(float a, float b) {
    __nv_bfloat162 t = __floats2bfloat162_rn(a, b);
    uint32_t r; memcpy(&r, &t, 4); return r;
}

// ---------------- small utility kernels -------------------------------------
__global__ void zero_f(float* p, int n) {
    int i = blockIdx.x * blockDim.x + threadIdx.x;
    if (i < n) p[i] = 0.f;
}
__global__ void zero_i(int* p, int n) {
    int i = blockIdx.x * blockDim.x + threadIdx.x;
    if (i < n) p[i] = 0;
}

__global__ void init_h_kernel(const int* __restrict__ x,
                              const float* __restrict__ ae1,
                              const float* __restrict__ ae2,
                              float* __restrict__ h, int n) {
    int idx = blockIdx.x * blockDim.x + threadIdx.x;
    if (idx >= n * EMB) return;
    int i = idx / EMB, c = idx - i * EMB;
    h[idx] = ae1[x[2 * i] * EMB + c] + ae2[x[2 * i + 1] * EMB + c];
}

__global__ void etab_kernel(const float* __restrict__ ee1,
                            const float* __restrict__ ee2,
                            float* __restrict__ et) {
    int idx = blockIdx.x * blockDim.x + threadIdx.x;
    if (idx >= NL * 18 * EMB) return;
    int l = idx / (18 * EMB);
    int r = idx - l * 18 * EMB;
    int combo = r / EMB, c = r - combo * EMB;
    int a0 = combo / 3, a1 = combo - a0 * 3;
    et[idx] = ee1[(size_t)l * 6 * EMB + a0 * EMB + c] +
              ee2[(size_t)l * 3 * EMB + a1 * EMB + c];
}

// ---------------- B table conversion ------------------------------------------
// src: trans=0 -> [K,N] row-major (weights), trans=1 -> [N,K] row-major (f1).
__global__ void conv_btab_kernel(const float* __restrict__ src,
                                 bf16* __restrict__ thi, bf16* __restrict__ tlo,
                                 int N, int K, int nkc, int trans, int total) {
    int idx = blockIdx.x * blockDim.x + threadIdx.x;
    if (idx >= total) return;
    int block  = idx >> 11;           // 2048 data elems per block
    int within = idx & 2047;
    int r = within >> 5, c = within & 31;
    int ntile = block / nkc, kc = block - ntile * nkc;
    int n = ntile * 64 + r;
    int k = kc * 32 + c;
    float v = 0.f;
    if (n < N && k < K)
        v = trans ? src[(size_t)n * K + k] : src[(size_t)k * N + n];
    bf16 h = __float2bfloat16_rn(v);
    size_t e = (size_t)block * BLKSZ + r * 40 + c;
    thi[e] = h;
    tlo[e] = __float2bfloat16_rn(v - __bfloat162float(h));
}

// feat0 fp32 -> hi/lo bf16 [NG, KP1]
__global__ void conv_f0_kernel(const float* __restrict__ f,
                               bf16* __restrict__ fh, bf16* __restrict__ fl) {
    int idx = blockIdx.x * blockDim.x + threadIdx.x;
    if (idx >= NG * EMB) return;
    int m = idx / EMB, k = idx - m * EMB;
    float v = f[idx];
    bf16 h = __float2bfloat16_rn(v);
    fh[(size_t)m * KP1 + k] = h;
    fl[(size_t)m * KP1 + k] = __float2bfloat16_rn(v - __bfloat162float(h));
}

// ---------------- hi/lo bf16 GEMM (mma.sync + ldmatrix + cp.async) ------------
// C = act(alpha * (Ah+Al) @ (Bh+Bl) + bias), 3-term compensated.
// Block tile 128x64, BK=32, 8 warps (4m x 2n), warp tile 32x32.
// 3 smem stages, ONE __syncthreads per chunk (prefetch distance 2).
#define STAGE_B   30720
#define GEMM_SMEM (3 * STAGE_B)

__global__ __launch_bounds__(256)
void gemm_hl_kernel(const bf16* __restrict__ Ahi, const bf16* __restrict__ Alo,
                    int Kpad, int nk,
                    const bf16* __restrict__ Bh, const bf16* __restrict__ Bl,
                    const float* __restrict__ bias,
                    float* __restrict__ Cf,
                    bf16* __restrict__ C3hi, bf16* __restrict__ C3lo, int K3out,
                    int M, int N, float alpha, int do_relu) {
    extern __shared__ uint32_t smem[];
    uint32_t sb = smem_addr_u32(smem);

    int tid = threadIdx.x, wid = tid >> 5, lane = tid & 31;
    int g = lane >> 2, tig = lane & 3;
    int wm = (wid & 3) * 32, wn = (wid >> 2) * 32;
    int bm0 = blockIdx.y * 128, bn0 = blockIdx.x * 64;

    float acc[2][4][4];
#pragma unroll
    for (int mt = 0; mt < 2; mt++)
#pragma unroll
        for (int nt = 0; nt < 4; nt++)
#pragma unroll
            for (int q = 0; q < 4; q++) acc[mt][nt][q] = 0.f;

    // ldmatrix per-lane address components (within a stage)
    //  A (m16k16 frag, x4): row = wm + mt*16 + (lane&15), koff = (lane>>4)*16
    int aRow  = wm + (lane & 15);
    int aKoff = (lane >> 4) * 16;
    //  B (two n8k16 frags per x4): row = wn + pr*16 + ((lane>>4)&1)*8 + (lane&7),
    //  koff = ((lane>>3)&1)*16
    int bRow  = wn + ((lane >> 4) & 1) * 8 + (lane & 7);
    int bKoff = ((lane >> 3) & 1) * 16;

    auto load_stage = [&](int kc, int s) {
        uint32_t base = sb + s * STAGE_B;
        // A: 128 rows x 32 k (hi+lo), row stride 80B, 4 chunks/row
#pragma unroll
        for (int it = 0; it < 2; it++) {
            int idx = tid + it * 256;             // 0..511
            int row = idx >> 2, ch = idx & 3;
            int gm = bm0 + row;
            int pred = gm < M;
            size_t so = (size_t)gm * Kpad + kc * 32 + ch * 8;
            uint32_t d = base + row * 80 + ch * 16;
            cp16(d, Ahi + so, pred);
            cp16(d + 10240, Alo + so, pred);
        }
        // B: flat 5120B block copies (tables pre-laid-out)
        const bf16* bh = Bh + (size_t)(blockIdx.x * nk + kc) * BLKSZ;
        const bf16* bl = Bl + (size_t)(blockIdx.x * nk + kc) * BLKSZ;
#pragma unroll
        for (int it = 0; it < 2; it++) {
            int idx = tid + it * 256;
            int pred = idx < 320;
            cp16(base + 20480 + idx * 16, bh + idx * 8, pred);
            cp16(base + 25600 + idx * 16, bl + idx * 8, pred);
        }
        asm volatile("cp.async.commit_group;" ::: "memory");
    };

    load_stage(0, 0);
    if (nk > 1) load_stage(1, 1);

    int stage = 0;
    for (int kc = 0; kc < nk; kc++) {
        asm volatile("cp.async.wait_group 1;" ::: "memory");
        __syncthreads();
        if (kc + 2 < nk) load_stage(kc + 2, (stage + 2) % 3);

        uint32_t base = sb + stage * STAGE_B;
        uint32_t aHi = base, aLo = base + 10240;
        uint32_t bHi = base + 20480, bLo = base + 25600;
#pragma unroll
        for (int s = 0; s < 2; s++) {
            int sk = s * 32;   // substep byte offset along k
            uint32_t ah[2][4], al[2][4], bh[4][2], bl[4][2];
#pragma unroll
            for (int mt = 0; mt < 2; mt++) {
                uint32_t aoff = (aRow + mt * 16) * 80 + sk + aKoff;
                LDSM4(ah[mt][0], ah[mt][1], ah[mt][2], ah[mt][3], aHi + aoff);
                LDSM4(al[mt][0], al[mt][1], al[mt][2], al[mt][3], aLo + aoff);
            }
#pragma unroll
            for (int pr = 0; pr < 2; pr++) {
                uint32_t boff = (bRow + pr * 16) * 80 + sk + bKoff;
                LDSM4(bh[pr * 2][0], bh[pr * 2][1], bh[pr * 2 + 1][0],
                      bh[pr * 2 + 1][1], bHi + boff);
                LDSM4(bl[pr * 2][0], bl[pr * 2][1], bl[pr * 2 + 1][0],
                      bl[pr * 2 + 1][1], bLo + boff);
            }
#pragma unroll
            for (int mt = 0; mt < 2; mt++)
#pragma unroll
                for (int nt = 0; nt < 4; nt++) {
                    mma_bf16(acc[mt][nt], ah[mt], bl[nt]);
                    mma_bf16(acc[mt][nt], al[mt], bh[nt]);
                    mma_bf16(acc[mt][nt], ah[mt], bh[nt]);
                }
        }
        stage = (stage + 1) % 3;
    }
    asm volatile("cp.async.wait_group 0;" ::: "memory");

    // ---- epilogue ----
#pragma unroll
    for (int mt = 0; mt < 2; mt++) {
        int gmB = bm0 + wm + mt * 16 + g;
#pragma unroll
        for (int nt = 0; nt < 4; nt++) {
            int n0 = bn0 + wn + nt * 8 + tig * 2;
            float* a = acc[mt][nt];
#pragma unroll
            for (int hf = 0; hf < 2; hf++) {
                int gm = gmB + hf * 8;
                if (gm >= M || n0 >= N) continue;
                float v0 = a[hf * 2] * alpha, v1 = a[hf * 2 + 1] * alpha;
                if (bias) { v0 += bias[n0]; v1 += bias[n0 + 1]; }
                if (do_relu) { v0 = fmaxf(v0, 0.f); v1 = fmaxf(v1, 0.f); }
                if (Cf) {
                    Cf[(size_t)gm * N + n0]     = v0;
                    Cf[(size_t)gm * N + n0 + 1] = v1;
                }
                if (C3hi) {
                    float h0 = __bfloat162float(__float2bfloat16_rn(v0));
                    float h1 = __bfloat162float(__float2bfloat16_rn(v1));
                    *(uint32_t*)(C3hi + (size_t)gm * K3out + n0) = packbf(h0, h1);
                    *(uint32_t*)(C3lo + (size_t)gm * K3out + n0) =
                        packbf(v0 - h0, v1 - h1);
                }
            }
        }
    }
}

// ---------------- CSR build ---------------------------------------------------
__global__ void count_deg_kernel(const int* __restrict__ ei, int* __restrict__ deg,
                                 int E) {
    int e = blockIdx.x * blockDim.x + threadIdx.x;
    if (e < E) atomicAdd(&deg[ei[E + e]], 1);
}

__global__ void scan1_kernel(const int* __restrict__ deg, int* __restrict__ off,
                             int* __restrict__ bsum, int n) {
    __shared__ int s[1024];
    int t = threadIdx.x;
    int i = blockIdx.x * 1024 + t;
    int v = (i < n) ? deg[i] : 0;
    s[t] = v;
    __syncthreads();
    for (int o = 1; o < 1024; o <<= 1) {
        int add = (t >= o) ? s[t - o] : 0;
        __syncthreads();
        s[t] += add;
        __syncthreads();
    }
    if (i < n) off[i + 1] = s[t];
    if (t == 1023) bsum[blockIdx.x] = s[1023];
}

__global__ void scan2_kernel(int* bsum, int G) {
    if (threadIdx.x == 0 && blockIdx.x == 0) {
        int run = 0;
        for (int b = 0; b < G; b++) { int v = bsum[b]; bsum[b] = run; run += v; }
    }
}

__global__ void scan3_kernel(int* __restrict__ off, const int* __restrict__ bsum,
                             int n) {
    int i = blockIdx.x * 1024 + threadIdx.x;
    if (i < n) off[i + 1] += bsum[blockIdx.x];
    if (i == 0) off[0] = 0;
}

__global__ void copy_cur_kernel(const int* __restrict__ off, int* __restrict__ cur,
                                int n) {
    int i = blockIdx.x * blockDim.x + threadIdx.x;
    if (i < n) cur[i] = off[i];
}

__global__ void fill_csr_kernel(const int* __restrict__ ei, const int* __restrict__ ea,
                                int* __restrict__ cur, int* __restrict__ csr, int E) {
    int e = blockIdx.x * blockDim.x + threadIdx.x;
    if (e >= E) return;
    int d = ei[E + e];
    int p = atomicAdd(&cur[d], 1);
    int a = ea[2 * e] * 3 + ea[2 * e + 1];
    csr[p] = ei[e] | (a << 20);
}

// ---------------- message aggregation: gather -> hi/lo bf16 -------------------
__global__ void gather_kernel(const float* __restrict__ h,
                              const int* __restrict__ off,
                              const int* __restrict__ csr,
                              const float* __restrict__ et,
                              bf16* __restrict__ ahi, bf16* __restrict__ alo,
                              int n) {
    int w    = (blockIdx.x * blockDim.x + threadIdx.x) >> 5;
    int lane = threadIdx.x & 31;
    if (w >= n) return;
    int o0 = off[w], o1 = off[w + 1];
    const float* hd    = h + (size_t)w * EMB;
    const float* selft = et + 12 * EMB;
    float r[10];
#pragma unroll
    for (int j = 0; j < 10; j++) {
        int c = lane + 32 * j;
        r[j] = (c < EMB) ? hd[c] + selft[c] : 0.f;
    }
    for (int o = o0; o < o1; o++) {
        int pk = csr[o];
        const float* hs = h  + (size_t)(pk & 0xFFFFF) * EMB;
        const float* tt = et + (size_t)(pk >> 20) * EMB;
#pragma unroll
        for (int j = 0; j < 10; j++) {
            int c = lane + 32 * j;
            if (c < EMB) r[j] += hs[c] + tt[c];
        }
    }
    bf16* rh = ahi + (size_t)w * KP1;
    bf16* rl = alo + (size_t)w * KP1;
#pragma unroll
    for (int j = 0; j < 10; j++) {
        int c = lane + 32 * j;
        if (c < EMB) {
            bf16 hh = __float2bfloat16_rn(r[j]);
            rh[c] = hh;
            rl[c] = __float2bfloat16_rn(r[j] - __bfloat162float(hh));
        }
    }
}

// ---------------- batchnorm ---------------------------------------------------
__global__ void bn_stats_kernel(const float* __restrict__ h, float* __restrict__ stats,
                                int n) {
    int t = threadIdx.x;
    if (t >= EMB) return;
    float s = 0.f, sq = 0.f;
    for (int r = blockIdx.x; r < n; r += gridDim.x) {
        float v = h[(size_t)r * EMB + t];
        s += v; sq += v * v;
    }
    atomicAdd(&stats[t], s);
    atomicAdd(&stats[EMB + t], sq);
}

// last layer additionally emits hi/lo bf16 for projector input
__global__ void bn_apply_kernel(float* __restrict__ h, const float* __restrict__ stats,
                                const float* __restrict__ gamma,
                                const float* __restrict__ beta,
                                int n, int do_relu,
                                bf16* __restrict__ ahi, bf16* __restrict__ alo) {
    int idx = blockIdx.x * blockDim.x + threadIdx.x;
    if (idx >= n * EMB) return;
    int i = idx / EMB, c = idx - i * EMB;
    float invn = 1.f / (float)n;
    float mean = stats[c] * invn;
    float var  = stats[EMB + c] * invn - mean * mean;
    float inv  = rsqrtf(var + BN_EPS);
    float v = (h[idx] - mean) * inv * gamma[c] + beta[c];
    if (do_relu) v = fmaxf(v, 0.f);
    h[idx] = v;
    if (ahi) {
        bf16 hh = __float2bfloat16_rn(v);
        ahi[(size_t)i * KP1 + c] = hh;
        alo[(size_t)i * KP1 + c] = __float2bfloat16_rn(v - __bfloat162float(hh));
    }
}

// ---------------- pooling + normalize ----------------------------------------
__global__ void pool_kernel(const float* __restrict__ p, const int* __restrict__ batch,
                            float* __restrict__ feat, float* __restrict__ cnt, int n) {
    int gw   = (blockIdx.x * blockDim.x + threadIdx.x) >> 5;
    int lane = threadIdx.x & 31;
    if (gw >= n) return;
    int b = batch[gw];
    if (lane == 0) atomicAdd(&cnt[b], 1.f);
    const float* pr = p + (size_t)gw * EMB;
    float* fr = feat + (size_t)b * EMB;
    for (int c = lane; c < EMB; c += 32) atomicAdd(fr + c, pr[c]);
}

__global__ void norm_feat_kernel(float* __restrict__ feat, const float* __restrict__ cnt) {
    __shared__ float red[16];
    int g = blockIdx.x, t = threadIdx.x;
    float c = fmaxf(cnt[g], 1.f);
    float v = 0.f;
    if (t < EMB) v = feat[(size_t)g * EMB + t] / c;
    float sq = v * v;
#pragma unroll
    for (int o = 16; o; o >>= 1) sq += __shfl_xor_sync(0xffffffffu, sq, o);
    if ((t & 31) == 0) red[t >> 5] = sq;
    __syncthreads();
    if (t < 32) {
        float s = (t < (int)(blockDim.x >> 5)) ? red[t] : 0.f;
#pragma unroll
        for (int o = 16; o; o >>= 1) s += __shfl_xor_sync(0xffffffffu, s, o);
        if (t == 0) red[0] = s;
    }
    __syncthreads();
    float nrm = fmaxf(sqrtf(red[0]), 1e-12f);
    if (t < EMB) feat[(size_t)g * EMB + t] = v / nrm;
}

// ---------------- driver ------------------------------------------------------
extern "C" void kernel_launch(void* const* d_in, const int* in_sizes, int n_in,
                              void* d_out, int out_size) {
    const int* x[2]  = {(const int*)d_in[0], (const int*)d_in[4]};
    const int* ei[2] = {(const int*)d_in[1], (const int*)d_in[5]};
    const int* ea[2] = {(const int*)d_in[2], (const int*)d_in[6]};
    const int* bt[2] = {(const int*)d_in[3], (const int*)d_in[7]};
    const float* ae1 = (const float*)d_in[8];
    const float* ae2 = (const float*)d_in[9];
    const float* ee1 = (const float*)d_in[10];
    const float* ee2 = (const float*)d_in[11];
    const float* w1  = (const float*)d_in[12];
    const float* b1  = (const float*)d_in[13];
    const float* w2  = (const float*)d_in[14];
    const float* b2  = (const float*)d_in[15];
    const float* gam = (const float*)d_in[16];
    const float* bet = (const float*)d_in[17];
    const float* pw  = (const float*)d_in[18];
    const float* pb  = (const float*)d_in[19];

    int Nn[2] = {in_sizes[0] / 2, in_sizes[4] / 2};
    int Ee[2] = {in_sizes[1] / 2, in_sizes[5] / 2};

    float *h, *agg, *stats, *feat0, *feat1, *cnt, *et;
    bf16 *ahi, *alo, *h2hi, *h2lo, *f0hi, *f0lo, *bthi, *btlo;
    int *off, *cur, *bsum, *csr;
    cudaGetSymbolAddress((void**)&h,     g_h);
    cudaGetSymbolAddress((void**)&agg,   g_agg);
    cudaGetSymbolAddress((void**)&stats, g_stats);
    cudaGetSymbolAddress((void**)&feat0, g_feat0);
    cudaGetSymbolAddress((void**)&feat1, g_feat1);
    cudaGetSymbolAddress((void**)&cnt,   g_cnt);
    cudaGetSymbolAddress((void**)&et,    g_etab);
    cudaGetSymbolAddress((void**)&ahi,   g_ahi);
    cudaGetSymbolAddress((void**)&alo,   g_alo);
    cudaGetSymbolAddress((void**)&h2hi,  g_h2hi);
    cudaGetSymbolAddress((void**)&h2lo,  g_h2lo);
    cudaGetSymbolAddress((void**)&f0hi,  g_f0hi);
    cudaGetSymbolAddress((void**)&f0lo,  g_f0lo);
    cudaGetSymbolAddress((void**)&bthi,  g_bthi);
    cudaGetSymbolAddress((void**)&btlo,  g_btlo);
    cudaGetSymbolAddress((void**)&off,   g_off);
    cudaGetSymbolAddress((void**)&cur,   g_cur);
    cudaGetSymbolAddress((void**)&bsum,  g_bsum);
    cudaGetSymbolAddress((void**)&csr,   g_csr);

    cudaFuncSetAttribute(gemm_hl_kernel,
                         cudaFuncAttributeMaxDynamicSharedMemorySize, GEMM_SMEM);

    etab_kernel<<<(NL * 18 * EMB + 255) / 256, 256>>>(ee1, ee2, et);

    // weight tables: hi/lo, smem-layout blocks
    for (int l = 0; l < NL; l++) {
        conv_btab_kernel<<<(100 * 2048 + 255) / 256, 256>>>(
            w1 + (size_t)l * EMB * EMB2, bthi + OFF_W1(l), btlo + OFF_W1(l),
            EMB2, EMB, NKC1, 0, 100 * 2048);
        conv_btab_kernel<<<(95 * 2048 + 255) / 256, 256>>>(
            w2 + (size_t)l * EMB2 * EMB, bthi + OFF_W2(l), btlo + OFF_W2(l),
            EMB, EMB2, NKC2, 0, 95 * 2048);
    }
    conv_btab_kernel<<<(50 * 2048 + 255) / 256, 256>>>(
        pw, bthi + OFF_PJ, btlo + OFF_PJ, EMB, EMB, NKC1, 0, 50 * 2048);

    for (int br = 0; br < 2; br++) {
        int n = Nn[br], e = Ee[br];
        float* feat_b = br ? feat1 : feat0;
        int elemBlocks = (n * EMB + 255) / 256;
        int G = (n + 1023) / 1024;
        int mt = (n + 127) / 128;

        // CSR (dst adjacency)
        zero_i<<<(n + 255) / 256, 256>>>(cur, n);
        count_deg_kernel<<<(e + 255) / 256, 256>>>(ei[br], cur, e);
        scan1_kernel<<<G, 1024>>>(cur, off, bsum, n);
        scan2_kernel<<<1, 32>>>(bsum, G);
        scan3_kernel<<<G, 1024>>>(off, bsum, n);
        copy_cur_kernel<<<(n + 255) / 256, 256>>>(off, cur, n);
        fill_csr_kernel<<<(e + 255) / 256, 256>>>(ei[br], ea[br], cur, csr, e);

        init_h_kernel<<<elemBlocks, 256>>>(x[br], ae1, ae2, h, n);

        for (int l = 0; l < NL; l++) {
            const float* etl = et + (size_t)l * 18 * EMB;

            gather_kernel<<<(n + 7) / 8, 256>>>(h, off, csr, etl, ahi, alo, n);

            // h2 = relu(agg @ W1 + b1) -> hi/lo bf16
            gemm_hl_kernel<<<dim3(10, mt), 256, GEMM_SMEM>>>(
                ahi, alo, KP1, NKC1, bthi + OFF_W1(l), btlo + OFF_W1(l),
                b1 + (size_t)l * EMB2, nullptr, h2hi, h2lo, KP2,
                n, EMB2, 1.f, 1);
            // h = h2 @ W2 + b2 (fp32)
            gemm_hl_kernel<<<dim3(5, mt), 256, GEMM_SMEM>>>(
                h2hi, h2lo, KP2, NKC2, bthi + OFF_W2(l), btlo + OFF_W2(l),
                b2 + (size_t)l * EMB, h, nullptr, nullptr, 0,
                n, EMB, 1.f, 0);

            zero_f<<<(2 * EMB + 255) / 256, 256>>>(stats, 2 * EMB);
            bn_stats_kernel<<<512, 320>>>(h, stats, n);
            bn_apply_kernel<<<elemBlocks, 256>>>(
                h, stats, gam + (size_t)l * EMB, bet + (size_t)l * EMB,
                n, l != NL - 1,
                (l == NL - 1) ? ahi : nullptr, (l == NL - 1) ? alo : nullptr);
        }

        // projector: agg = h @ proj_w + proj_b
        gemm_hl_kernel<<<dim3(5, mt), 256, GEMM_SMEM>>>(
            ahi, alo, KP1, NKC1, bthi + OFF_PJ, btlo + OFF_PJ,
            pb, agg, nullptr, nullptr, 0, n, EMB, 1.f, 0);

        zero_f<<<(NG * EMB + 255) / 256, 256>>>(feat_b, NG * EMB);
        zero_f<<<(NG + 255) / 256, 256>>>(cnt, NG);
        pool_kernel<<<(n * 32 + 255) / 256, 256>>>(agg, bt[br], feat_b, cnt, n);
        norm_feat_kernel<<<NG, 320>>>(feat_b, cnt);
    }

    // logits = f0 @ f1^T / TEMP
    conv_btab_kernel<<<(640 * 2048 + 255) / 256, 256>>>(
        feat1, bthi + OFF_F1, btlo + OFF_F1, NG, EMB, NKC1, 1, 640 * 2048);
    conv_f0_kernel<<<(NG * EMB + 255) / 256, 256>>>(feat0, f0hi, f0lo);
    gemm_hl_kernel<<<dim3(64, 32), 256, GEMM_SMEM>>>(
        f0hi, f0lo, KP1, NKC1, bthi + OFF_F1, btlo + OFF_F1,
        nullptr, (float*)d_out, nullptr, nullptr, 0,
        NG, NG, INV_TEMP, 0);
}